// round 8
// baseline (speedup 1.0000x reference)
#include <cuda_runtime.h>

// Problem constants (fixed by the reference module)
#define BATCH 8
#define LNODES 512
#define CHAN 6
#define KNN 9
#define NTOT (BATCH * LNODES)          // 4096
#define NK   (NTOT * KNN)              // 36864
#define BIGF 1.0e10f

// Output layout (flattened concatenation of the reference's returned tuple,
// all cast to float32):
//   [0*NK, 1*NK)  dknn
//   [1*NK, 2*NK)  src
//   [2*NK, 3*NK)  dst (-1 where invalid)
//   [3*NK, 4*NK)  valid (0/1)
//   [OFF_G, +16368)  glb_edges  [2, B*(2L-1)] row-major
//   [OFF_S, +16320)  seq_edges  [2, B*2(L-2)] row-major
#define OFF_G (4 * NK)                 // 147456
#define GLB_PER_B (2 * LNODES - 1)     // 1023
#define GLB_ROW (BATCH * GLB_PER_B)    // 8184
#define GLB_TOT (2 * GLB_ROW)          // 16368
#define OFF_S (OFF_G + GLB_TOT)        // 163824
#define SEQ_PER_B (2 * (LNODES - 2))   // 1020
#define SEQ_ROW (BATCH * SEQ_PER_B)    // 8160
#define SEQ_TOT (2 * SEQ_ROW)          // 16320

__device__ __forceinline__ unsigned long long umin64(unsigned long long a,
                                                     unsigned long long b) {
    return a < b ? a : b;
}

// One block per row i. Thread j computes dist(i, j) for j = threadIdx.x,
// then 9 cooperative argmin rounds pick the k smallest (ties -> smaller j,
// matching jax.lax.top_k stability on -dist).
__global__ __launch_bounds__(LNODES) void knn_kernel(
    const float* __restrict__ X,     // [N, C, 3]
    const int*   __restrict__ AP,    // [N, C]
    const int*   __restrict__ S,     // [N]
    const int*   __restrict__ secp,  // [N]
    float*       __restrict__ out)
{
    const int i   = blockIdx.x;          // global row (node) index
    const int b   = i / LNODES;
    const int tid = threadIdx.x;         // local column j within the graph
    const int lane = tid & 31;
    const int wid  = tid >> 5;

    __shared__ float xi[CHAN][3];
    __shared__ float sqi[CHAN];
    __shared__ int   padi[CHAN];
    __shared__ int   si;
    __shared__ unsigned long long warpmin[16];
    __shared__ unsigned long long winner_sh;
    __shared__ unsigned long long res[KNN];

    if (tid < CHAN) {
        float a0 = X[i * (CHAN * 3) + tid * 3 + 0];
        float a1 = X[i * (CHAN * 3) + tid * 3 + 1];
        float a2 = X[i * (CHAN * 3) + tid * 3 + 2];
        xi[tid][0] = a0; xi[tid][1] = a1; xi[tid][2] = a2;
        sqi[tid]  = a0 * a0 + a1 * a1 + a2 * a2;
        padi[tid] = (AP[i * CHAN + tid] == 0);
    }
    if (tid == CHAN) si = S[i];
    __syncthreads();

    // ---- distance(i, j) for this thread's j ----
    const int n = b * LNODES + tid;      // global column node index
    float xj[CHAN][3], sqj[CHAN];
    int padj[CHAN];
#pragma unroll
    for (int c = 0; c < CHAN; ++c) {
        float a0 = X[n * (CHAN * 3) + c * 3 + 0];
        float a1 = X[n * (CHAN * 3) + c * 3 + 1];
        float a2 = X[n * (CHAN * 3) + c * 3 + 2];
        xj[c][0] = a0; xj[c][1] = a1; xj[c][2] = a2;
        sqj[c]  = a0 * a0 + a1 * a1 + a2 * a2;
        padj[c] = (AP[n * CHAN + c] == 0);
    }

    float m2 = 3.4e38f;
    int   any = 0;
#pragma unroll
    for (int c = 0; c < CHAN; ++c) {
        float xc0 = xi[c][0], xc1 = xi[c][1], xc2 = xi[c][2];
        float sc  = sqi[c];
        int   pc  = padi[c];
#pragma unroll
        for (int d = 0; d < CHAN; ++d) {
            float dot = xc0 * xj[d][0] + xc1 * xj[d][1] + xc2 * xj[d][2];
            float d2  = sc + sqj[d] - 2.0f * dot;
            int ok = (!pc) & (!padj[d]);
            if (ok) { m2 = fminf(m2, d2); any = 1; }
        }
    }

    float dist = any ? sqrtf(fmaxf(m2, 0.0f)) : BIGF;
    // global-node (BOS) mask: either endpoint being BOS -> exactly 1e10f
    if (si == 0 || S[n] == 0) dist = BIGF;

    // pack: (dist bits << 32) | local index. dist >= 0 so float-bit order
    // == unsigned order; ties break toward smaller j (top_k stability).
    unsigned long long key =
        ((unsigned long long)__float_as_uint(dist) << 32) | (unsigned)tid;

    // ---- 9 argmin rounds ----
    for (int r = 0; r < KNN; ++r) {
        unsigned long long v = key;
#pragma unroll
        for (int off = 16; off > 0; off >>= 1)
            v = umin64(v, __shfl_xor_sync(0xffffffffu, v, off));
        if (lane == 0) warpmin[wid] = v;
        __syncthreads();
        if (wid == 0) {
            unsigned long long w = (lane < 16) ? warpmin[lane] : ~0ULL;
#pragma unroll
            for (int off = 8; off > 0; off >>= 1)
                w = umin64(w, __shfl_xor_sync(0xffffffffu, w, off));
            if (lane == 0) { winner_sh = w; res[r] = w; }
        }
        __syncthreads();
        unsigned long long w = winner_sh;
        if ((unsigned)(w & 0xffffffffu) == (unsigned)tid) key = ~0ULL;
    }

    // ---- write outputs for this row ----
    if (tid < KNN) {
        unsigned long long w = res[tid];
        float d   = __uint_as_float((unsigned)(w >> 32));
        int   jl  = (int)(w & 0xffffffffu);
        int   dg  = b * LNODES + jl;
        int   val = (d < BIGF) && (secp[i] == secp[dg]);
        int   o   = i * KNN + tid;
        out[0 * NK + o] = d;
        out[1 * NK + o] = (float)i;
        out[2 * NK + o] = val ? (float)dg : -1.0f;
        out[3 * NK + o] = (float)val;
    }
}

// Pure index formulas for glb_edges and seq_edges.
__global__ void edges_kernel(float* __restrict__ out)
{
    int t = blockIdx.x * blockDim.x + threadIdx.x;
    if (t < GLB_TOT) {
        int r = t / GLB_ROW;
        int q = t - r * GLB_ROW;
        int b = q / GLB_PER_B;
        int u = q - b * GLB_PER_B;
        int src_l = (u < LNODES) ? 0 : (u - (LNODES - 1));
        int dst_l = (u < LNODES) ? u : 0;
        int v = ((r == 0) ? src_l : dst_l) + b * LNODES;
        out[OFF_G + t] = (float)v;
        return;
    }
    int s = t - GLB_TOT;
    if (s < SEQ_TOT) {
        int r = s / SEQ_ROW;
        int q = s - r * SEQ_ROW;
        int b = q / SEQ_PER_B;
        int u = q - b * SEQ_PER_B;
        int half = LNODES - 2;           // 510
        int src_l, dst_l;
        if (u < half) { src_l = u + 1; dst_l = u + 2; }
        else          { src_l = u - half + 2; dst_l = u - half + 1; }
        int v = ((r == 0) ? src_l : dst_l) + b * LNODES;
        out[OFF_S + s] = (float)v;
    }
}

extern "C" void kernel_launch(void* const* d_in, const int* in_sizes, int n_in,
                              void* d_out, int out_size)
{
    const float* X    = (const float*)d_in[0];   // [N, C, 3] f32
    const int*   AP   = (const int*)  d_in[1];   // [N, C]    i32
    const int*   S    = (const int*)  d_in[2];   // [N]       i32
    const int*   secp = (const int*)  d_in[3];   // [N]       i32
    // d_in[4] = batch_id (unused: implied by layout), d_in[5] = k (fixed 9)
    float* out = (float*)d_out;

    knn_kernel<<<NTOT, LNODES>>>(X, AP, S, secp, out);

    const int edge_elems = GLB_TOT + SEQ_TOT;    // 32688
    edges_kernel<<<(edge_elems + 255) / 256, 256>>>(out);
}

// round 10
// speedup vs baseline: 2.3791x; 2.3791x over previous
#include <cuda_runtime.h>

// Problem constants (fixed by the reference module)
#define BATCH 8
#define LNODES 512
#define CHAN 6
#define KNN 9
#define NTOT (BATCH * LNODES)          // 4096
#define NK   (NTOT * KNN)              // 36864
#define BIGF 1.0e10f

// Output layout (flattened reference tuple, all float32)
#define OFF_G (4 * NK)                 // 147456
#define GLB_PER_B (2 * LNODES - 1)     // 1023
#define GLB_ROW (BATCH * GLB_PER_B)    // 8184
#define GLB_TOT (2 * GLB_ROW)          // 16368
#define OFF_S (OFF_G + GLB_TOT)        // 163824
#define SEQ_PER_B (2 * (LNODES - 2))   // 1020
#define SEQ_ROW (BATCH * SEQ_PER_B)    // 8160
#define SEQ_TOT (2 * SEQ_ROW)          // 16320

#define WARPS_PER_BLK 8
#define TPB (WARPS_PER_BLK * 32)       // 256
#define NBLK (NTOT / WARPS_PER_BLK)    // 512
#define COLS_PER_LANE (LNODES / 32)    // 16

__device__ __forceinline__ unsigned long long umin64(unsigned long long a,
                                                     unsigned long long b) {
    return a < b ? a : b;
}

// One WARP per row i. Lane l owns columns j = l + 32q, q = 0..15.
// Per-lane register top-9 (stable compare-swap cascade on (dist, j)),
// then 9 warp-shuffle argmin merge rounds. No shared memory, no barriers.
__global__ __launch_bounds__(TPB) void knn_kernel(
    const float* __restrict__ X,     // [N, C, 3]
    const int*   __restrict__ AP,    // [N, C]
    const int*   __restrict__ S,     // [N]
    const int*   __restrict__ secp,  // [N]
    float*       __restrict__ out)
{
    const int tid  = threadIdx.x;
    const int lane = tid & 31;
    const int wid  = tid >> 5;
    const int gtid = blockIdx.x * TPB + tid;

    // ---- fused edge-formula outputs (replaces the old second kernel) ----
    if (gtid < GLB_TOT + SEQ_TOT) {
        if (gtid < GLB_TOT) {
            int t = gtid;
            int r = t / GLB_ROW;
            int q = t - r * GLB_ROW;
            int b = q / GLB_PER_B;
            int u = q - b * GLB_PER_B;
            int src_l = (u < LNODES) ? 0 : (u - (LNODES - 1));
            int dst_l = (u < LNODES) ? u : 0;
            int v = ((r == 0) ? src_l : dst_l) + b * LNODES;
            out[OFF_G + t] = (float)v;
        } else {
            int s = gtid - GLB_TOT;
            int r = s / SEQ_ROW;
            int q = s - r * SEQ_ROW;
            int b = q / SEQ_PER_B;
            int u = q - b * SEQ_PER_B;
            int half = LNODES - 2;       // 510
            int src_l, dst_l;
            if (u < half) { src_l = u + 1; dst_l = u + 2; }
            else          { src_l = u - half + 2; dst_l = u - half + 1; }
            int v = ((r == 0) ? src_l : dst_l) + b * LNODES;
            out[OFF_S + s] = (float)v;
        }
    }

    // ---- row setup ----
    const int i    = blockIdx.x * WARPS_PER_BLK + wid;   // global row
    const int b    = i >> 9;
    const int base = b << 9;

    float xi[CHAN][3];
    float sci[CHAN];                 // sq_i + 1e30 sentinel when channel padded
#pragma unroll
    for (int c = 0; c < CHAN; ++c) {
        float a0 = X[i * (CHAN * 3) + c * 3 + 0];
        float a1 = X[i * (CHAN * 3) + c * 3 + 1];
        float a2 = X[i * (CHAN * 3) + c * 3 + 2];
        xi[c][0] = a0; xi[c][1] = a1; xi[c][2] = a2;
        float sq = a0 * a0 + a1 * a1 + a2 * a2;
        sci[c] = sq + ((AP[i * CHAN + c] == 0) ? 1e30f : 0.0f);
    }
    const int rowBOS = (S[i] == 0);

    // ---- per-lane sorted top-9 (ascending (dist, j)) ----
    float dt[KNN];
    int   it[KNN];
#pragma unroll
    for (int s = 0; s < KNN; ++s) { dt[s] = __int_as_float(0x7f800000); it[s] = LNODES - 1; }

#pragma unroll 2
    for (int q = 0; q < COLS_PER_LANE; ++q) {
        const int j = lane + (q << 5);           // ascending in q per lane
        const int n = base + j;

        // node j data: 18 floats (9 x float2, 8B-aligned since 18 even)
        const float2* xp = (const float2*)(X + n * (CHAN * 3));
        float f[18];
#pragma unroll
        for (int t = 0; t < 9; ++t) {
            float2 v = xp[t];
            f[2 * t] = v.x; f[2 * t + 1] = v.y;
        }
        const int2* ap = (const int2*)(AP + n * CHAN);
        int2 a01 = ap[0], a23 = ap[1], a45 = ap[2];
        int apd[CHAN] = { a01.x, a01.y, a23.x, a23.y, a45.x, a45.y };

        float sqj[CHAN];
#pragma unroll
        for (int d = 0; d < CHAN; ++d) {
            float x0 = f[d * 3], x1 = f[d * 3 + 1], x2 = f[d * 3 + 2];
            float sq = x0 * x0 + x1 * x1 + x2 * x2;
            sqj[d] = sq + ((apd[d] == 0) ? 1e30f : 0.0f);
        }

        float m2 = 3.4e38f;
#pragma unroll
        for (int c = 0; c < CHAN; ++c) {
            float xc0 = xi[c][0], xc1 = xi[c][1], xc2 = xi[c][2];
            float sc  = sci[c];
#pragma unroll
            for (int d = 0; d < CHAN; ++d) {
                float dot = xc0 * f[d * 3]
                          + xc1 * f[d * 3 + 1]
                          + xc2 * f[d * 3 + 2];
                float d2  = fmaf(dot, -2.0f, sc + sqj[d]);
                m2 = fminf(m2, d2);
            }
        }

        float dist = (m2 >= 1e20f) ? BIGF : sqrtf(fmaxf(m2, 0.0f));
        if (rowBOS | (S[n] == 0)) dist = BIGF;

        // stable insertion (strict <): equal dists keep earlier (smaller j) first
        float kd = dist; int ki = j;
#pragma unroll
        for (int s = 0; s < KNN; ++s) {
            bool cc = kd < dt[s];
            float dl = cc ? kd : dt[s];
            float dh = cc ? dt[s] : kd;
            int   il = cc ? ki : it[s];
            int   ih = cc ? it[s] : ki;
            dt[s] = dl; it[s] = il; kd = dh; ki = ih;
        }
    }

    // ---- warp merge: 9 argmin rounds over lane heads ----
    unsigned long long wr = 0;
#pragma unroll
    for (int r = 0; r < KNN; ++r) {
        unsigned long long key =
            ((unsigned long long)__float_as_uint(dt[0]) << 32) | (unsigned)it[0];
        unsigned long long v = key;
#pragma unroll
        for (int off = 16; off > 0; off >>= 1)
            v = umin64(v, __shfl_xor_sync(0xffffffffu, v, off));
        bool win = (key == v);                   // unique: j distinct per lane
#pragma unroll
        for (int s = 0; s < KNN - 1; ++s) {
            dt[s] = win ? dt[s + 1] : dt[s];
            it[s] = win ? it[s + 1] : it[s];
        }
        if (win) { dt[KNN - 1] = __int_as_float(0x7f800000); it[KNN - 1] = LNODES - 1; }
        if (lane == r) wr = v;
    }

    // ---- outputs: lanes 0..8 each own one k-slot ----
    if (lane < KNN) {
        float d  = __uint_as_float((unsigned)(wr >> 32));
        int   jl = (int)(wr & 0xffffffffu);
        int   dg = base + jl;
        int   val = (d < BIGF) && (secp[i] == secp[dg]);
        int   o   = i * KNN + lane;
        out[0 * NK + o] = d;
        out[1 * NK + o] = (float)i;
        out[2 * NK + o] = val ? (float)dg : -1.0f;
        out[3 * NK + o] = (float)val;
    }
}

extern "C" void kernel_launch(void* const* d_in, const int* in_sizes, int n_in,
                              void* d_out, int out_size)
{
    const float* X    = (const float*)d_in[0];   // [N, C, 3] f32
    const int*   AP   = (const int*)  d_in[1];   // [N, C]    i32
    const int*   S    = (const int*)  d_in[2];   // [N]       i32
    const int*   secp = (const int*)  d_in[3];   // [N]       i32
    float* out = (float*)d_out;

    knn_kernel<<<NBLK, TPB>>>(X, AP, S, secp, out);
}